// round 1
// baseline (speedup 1.0000x reference)
#include <cuda_runtime.h>
#include <math.h>
#include <stdint.h>

// Problem dims (fixed for this problem instance)
#define T_TOK 2048
#define H_DIM 1024
#define F_DIM 4096
#define E_NUM 8
#define CAP   2048          // worst-case tokens per expert

// GEMM tiling
#define BM 128
#define BN 128
#define BK 16
#define ASTR 20             // As row stride (floats) -> conflict-free A-frag LDS
#define BSTR 136            // Bs row stride (floats) -> conflict-free B-frag LDS

// -------- device scratch (allocation-free rule: __device__ globals) --------
__device__ int   d_cnt[E_NUM];
__device__ int   d_tok[E_NUM * CAP];
__device__ float d_wt [E_NUM * CAP];
__device__ float d_hbuf[(size_t)E_NUM * CAP * F_DIM];   // 256 MB, h in tf32 bits

// -------- helpers --------
__device__ __forceinline__ unsigned f2tf(float f) {
    unsigned u;
    asm("cvt.rna.tf32.f32 %0, %1;" : "=r"(u) : "f"(f));
    return u;
}

__device__ __forceinline__ void mma_tf32(float c[4], const unsigned a[4], const unsigned b[2]) {
    asm volatile(
        "mma.sync.aligned.m16n8k8.row.col.f32.tf32.tf32.f32 "
        "{%0,%1,%2,%3}, {%4,%5,%6,%7}, {%8,%9}, {%0,%1,%2,%3};\n"
        : "+f"(c[0]), "+f"(c[1]), "+f"(c[2]), "+f"(c[3])
        : "r"(a[0]), "r"(a[1]), "r"(a[2]), "r"(a[3]), "r"(b[0]), "r"(b[1]));
}

// -------- kernel 0: zero output + counters --------
__global__ void moe_zero_kernel(float* __restrict__ out) {
    int i = blockIdx.x * blockDim.x + threadIdx.x;
    if (i < E_NUM) d_cnt[i] = 0;
    int stride = gridDim.x * blockDim.x;
    for (int j = i; j < T_TOK * H_DIM; j += stride) out[j] = 0.0f;
}

// -------- kernel 1: router (one block per token) --------
__global__ __launch_bounds__(256) void moe_router_kernel(
    const float* __restrict__ x, const float* __restrict__ gw,
    const float* __restrict__ gb)
{
    __shared__ float xs[H_DIM];
    __shared__ float lg[E_NUM];
    int t = blockIdx.x;
    const float4* xr = (const float4*)(x + (size_t)t * H_DIM);
    for (int i = threadIdx.x; i < H_DIM / 4; i += blockDim.x)
        ((float4*)xs)[i] = xr[i];
    __syncthreads();

    int w = threadIdx.x >> 5, lane = threadIdx.x & 31;
    if (w < E_NUM) {
        float s = 0.0f;
        for (int h = lane; h < H_DIM; h += 32) s += xs[h] * gw[h * E_NUM + w];
        #pragma unroll
        for (int o = 16; o; o >>= 1) s += __shfl_down_sync(0xffffffffu, s, o);
        if (lane == 0) lg[w] = s + gb[w];
    }
    __syncthreads();

    if (threadIdx.x == 0) {
        int i1 = 0; float l1 = lg[0];
        #pragma unroll
        for (int e = 1; e < E_NUM; e++) if (lg[e] > l1) { l1 = lg[e]; i1 = e; }
        int i2 = -1; float l2 = -1e30f;
        #pragma unroll
        for (int e = 0; e < E_NUM; e++)
            if (e != i1 && lg[e] > l2) { l2 = lg[e]; i2 = e; }
        // softmax over 8 then renorm top-2 == 2-way softmax of top-2 logits
        float p1 = 1.0f / (1.0f + expf(l2 - l1));
        float p2 = 1.0f - p1;
        int pos1 = atomicAdd(&d_cnt[i1], 1);
        d_tok[i1 * CAP + pos1] = t;  d_wt[i1 * CAP + pos1] = p1;
        int pos2 = atomicAdd(&d_cnt[i2], 1);
        d_tok[i2 * CAP + pos2] = t;  d_wt[i2 * CAP + pos2] = p2;
    }
}

// -------- kernel 2: GEMM1  h = relu(X_gather @ W1[e] + b1[e]) --------
__global__ __launch_bounds__(256) void moe_ffn1_kernel(
    const float* __restrict__ x, const float* __restrict__ w1,
    const float* __restrict__ b1)
{
    int e  = blockIdx.z;
    int M  = d_cnt[e];
    int m0 = blockIdx.y * BM;
    if (m0 >= M) return;
    int n0 = blockIdx.x * BN;

    __shared__ unsigned As[BM * ASTR];
    __shared__ unsigned Bs[BK * BSTR];

    int tid  = threadIdx.x;
    int warp = tid >> 5, lane = tid & 31;
    int wm = warp >> 1, wn = warp & 1;      // 4x2 warps, warp tile 32x64
    int grp = lane >> 2, t4 = lane & 3;

    // A-load mapping: lin = i*256+tid; m = lin>>2; k4 = lin&3
    int k4 = tid & 3;
    int mA[2];  int tokA[2];
    #pragma unroll
    for (int i = 0; i < 2; i++) {
        mA[i] = (tid >> 2) + i * 64;
        int gm = m0 + mA[i];
        tokA[i] = (gm < M) ? d_tok[e * CAP + gm] : 0;
    }
    // B-load mapping: lin = i*256+tid; k = lin>>5; n4 = lin&31
    int n4b = tid & 31;
    int kB[2] = { (tid >> 5), (tid >> 5) + 8 };

    float acc[2][8][4];
    #pragma unroll
    for (int mi = 0; mi < 2; mi++)
        #pragma unroll
        for (int ni = 0; ni < 8; ni++)
            #pragma unroll
            for (int j = 0; j < 4; j++) acc[mi][ni][j] = 0.0f;

    for (int k0 = 0; k0 < H_DIM; k0 += BK) {
        #pragma unroll
        for (int i = 0; i < 2; i++) {
            float4 v = *(const float4*)(x + (size_t)tokA[i] * H_DIM + k0 + k4 * 4);
            unsigned* dst = &As[mA[i] * ASTR + k4 * 4];
            dst[0] = f2tf(v.x); dst[1] = f2tf(v.y); dst[2] = f2tf(v.z); dst[3] = f2tf(v.w);
        }
        #pragma unroll
        for (int i = 0; i < 2; i++) {
            float4 v = *(const float4*)(w1 + (size_t)(e * H_DIM + k0 + kB[i]) * F_DIM + n0 + n4b * 4);
            unsigned* dst = &Bs[kB[i] * BSTR + n4b * 4];
            dst[0] = f2tf(v.x); dst[1] = f2tf(v.y); dst[2] = f2tf(v.z); dst[3] = f2tf(v.w);
        }
        __syncthreads();

        #pragma unroll
        for (int kk = 0; kk < BK; kk += 8) {
            unsigned a[2][4], b[8][2];
            #pragma unroll
            for (int mi = 0; mi < 2; mi++) {
                int mb = wm * 32 + mi * 16;
                a[mi][0] = As[(mb + grp    ) * ASTR + kk + t4    ];
                a[mi][1] = As[(mb + grp + 8) * ASTR + kk + t4    ];
                a[mi][2] = As[(mb + grp    ) * ASTR + kk + t4 + 4];
                a[mi][3] = As[(mb + grp + 8) * ASTR + kk + t4 + 4];
            }
            #pragma unroll
            for (int ni = 0; ni < 8; ni++) {
                int nb = wn * 64 + ni * 8 + grp;
                b[ni][0] = Bs[(kk + t4    ) * BSTR + nb];
                b[ni][1] = Bs[(kk + t4 + 4) * BSTR + nb];
            }
            #pragma unroll
            for (int mi = 0; mi < 2; mi++)
                #pragma unroll
                for (int ni = 0; ni < 8; ni++)
                    mma_tf32(acc[mi][ni], a[mi], b[ni]);
        }
        __syncthreads();
    }

    // epilogue: bias + relu, store as tf32 bits (GEMM2 input, pre-converted)
    #pragma unroll
    for (int mi = 0; mi < 2; mi++) {
        int r0 = m0 + wm * 32 + mi * 16 + grp;
        #pragma unroll
        for (int ni = 0; ni < 8; ni++) {
            int c = n0 + wn * 64 + ni * 8 + t4 * 2;
            float bb0 = b1[e * F_DIM + c];
            float bb1 = b1[e * F_DIM + c + 1];
            if (r0 < M) {
                unsigned* hp = (unsigned*)&d_hbuf[(size_t)(e * CAP + r0) * F_DIM + c];
                hp[0] = f2tf(fmaxf(acc[mi][ni][0] + bb0, 0.0f));
                hp[1] = f2tf(fmaxf(acc[mi][ni][1] + bb1, 0.0f));
            }
            if (r0 + 8 < M) {
                unsigned* hp = (unsigned*)&d_hbuf[(size_t)(e * CAP + r0 + 8) * F_DIM + c];
                hp[0] = f2tf(fmaxf(acc[mi][ni][2] + bb0, 0.0f));
                hp[1] = f2tf(fmaxf(acc[mi][ni][3] + bb1, 0.0f));
            }
        }
    }
}

// -------- kernel 3: GEMM2  out[tok] += wt * (h @ W2[e] + b2[e]) --------
__global__ __launch_bounds__(256) void moe_ffn2_kernel(
    const float* __restrict__ w2, const float* __restrict__ b2,
    float* __restrict__ out)
{
    int e  = blockIdx.z;
    int M  = d_cnt[e];
    int m0 = blockIdx.y * BM;
    if (m0 >= M) return;
    int n0 = blockIdx.x * BN;

    __shared__ unsigned As[BM * ASTR];
    __shared__ unsigned Bs[BK * BSTR];

    int tid  = threadIdx.x;
    int warp = tid >> 5, lane = tid & 31;
    int wm = warp >> 1, wn = warp & 1;
    int grp = lane >> 2, t4 = lane & 3;

    int k4 = tid & 3;
    int mA[2] = { (tid >> 2), (tid >> 2) + 64 };
    int n4b = tid & 31;
    int kB[2] = { (tid >> 5), (tid >> 5) + 8 };

    float acc[2][8][4];
    #pragma unroll
    for (int mi = 0; mi < 2; mi++)
        #pragma unroll
        for (int ni = 0; ni < 8; ni++)
            #pragma unroll
            for (int j = 0; j < 4; j++) acc[mi][ni][j] = 0.0f;

    for (int k0 = 0; k0 < F_DIM; k0 += BK) {
        #pragma unroll
        for (int i = 0; i < 2; i++) {
            // h already stored as tf32 bit patterns: raw copy
            uint4 v = *(const uint4*)(d_hbuf + (size_t)(e * CAP + m0 + mA[i]) * F_DIM + k0 + k4 * 4);
            unsigned* dst = &As[mA[i] * ASTR + k4 * 4];
            dst[0] = v.x; dst[1] = v.y; dst[2] = v.z; dst[3] = v.w;
        }
        #pragma unroll
        for (int i = 0; i < 2; i++) {
            float4 v = *(const float4*)(w2 + (size_t)(e * F_DIM + k0 + kB[i]) * H_DIM + n0 + n4b * 4);
            unsigned* dst = &Bs[kB[i] * BSTR + n4b * 4];
            dst[0] = f2tf(v.x); dst[1] = f2tf(v.y); dst[2] = f2tf(v.z); dst[3] = f2tf(v.w);
        }
        __syncthreads();

        #pragma unroll
        for (int kk = 0; kk < BK; kk += 8) {
            unsigned a[2][4], b[8][2];
            #pragma unroll
            for (int mi = 0; mi < 2; mi++) {
                int mb = wm * 32 + mi * 16;
                a[mi][0] = As[(mb + grp    ) * ASTR + kk + t4    ];
                a[mi][1] = As[(mb + grp + 8) * ASTR + kk + t4    ];
                a[mi][2] = As[(mb + grp    ) * ASTR + kk + t4 + 4];
                a[mi][3] = As[(mb + grp + 8) * ASTR + kk + t4 + 4];
            }
            #pragma unroll
            for (int ni = 0; ni < 8; ni++) {
                int nb = wn * 64 + ni * 8 + grp;
                b[ni][0] = Bs[(kk + t4    ) * BSTR + nb];
                b[ni][1] = Bs[(kk + t4 + 4) * BSTR + nb];
            }
            #pragma unroll
            for (int mi = 0; mi < 2; mi++)
                #pragma unroll
                for (int ni = 0; ni < 8; ni++)
                    mma_tf32(acc[mi][ni], a[mi], b[ni]);
        }
        __syncthreads();
    }

    // epilogue: bias, weight, scatter-add into output (2 adds/element -> deterministic)
    #pragma unroll
    for (int mi = 0; mi < 2; mi++) {
        int r0 = m0 + wm * 32 + mi * 16 + grp;
        int r1 = r0 + 8;
        bool v0r = (r0 < M), v1r = (r1 < M);
        int tok0 = 0, tok1 = 0; float wt0 = 0.0f, wt1 = 0.0f;
        if (v0r) { tok0 = d_tok[e * CAP + r0]; wt0 = d_wt[e * CAP + r0]; }
        if (v1r) { tok1 = d_tok[e * CAP + r1]; wt1 = d_wt[e * CAP + r1]; }
        #pragma unroll
        for (int ni = 0; ni < 8; ni++) {
            int c = n0 + wn * 64 + ni * 8 + t4 * 2;
            float bb0 = b2[e * H_DIM + c];
            float bb1 = b2[e * H_DIM + c + 1];
            if (v0r) {
                atomicAdd(&out[(size_t)tok0 * H_DIM + c    ], wt0 * (acc[mi][ni][0] + bb0));
                atomicAdd(&out[(size_t)tok0 * H_DIM + c + 1], wt0 * (acc[mi][ni][1] + bb1));
            }
            if (v1r) {
                atomicAdd(&out[(size_t)tok1 * H_DIM + c    ], wt1 * (acc[mi][ni][2] + bb0));
                atomicAdd(&out[(size_t)tok1 * H_DIM + c + 1], wt1 * (acc[mi][ni][3] + bb1));
            }
        }
    }
}

// -------- launch --------
extern "C" void kernel_launch(void* const* d_in, const int* in_sizes, int n_in,
                              void* d_out, int out_size) {
    const float* x  = (const float*)d_in[0];
    const float* gw = (const float*)d_in[1];
    const float* gb = (const float*)d_in[2];
    const float* w1 = (const float*)d_in[3];
    const float* b1 = (const float*)d_in[4];
    const float* w2 = (const float*)d_in[5];
    const float* b2 = (const float*)d_in[6];
    float* out = (float*)d_out;

    moe_zero_kernel<<<512, 256>>>(out);
    moe_router_kernel<<<T_TOK, 256>>>(x, gw, gb);
    dim3 g1(F_DIM / BN, CAP / BM, E_NUM);
    moe_ffn1_kernel<<<g1, 256>>>(x, w1, b1);
    dim3 g2(H_DIM / BN, CAP / BM, E_NUM);
    moe_ffn2_kernel<<<g2, 256>>>(w2, b2, out);
}

// round 3
// speedup vs baseline: 1.5993x; 1.5993x over previous
#include <cuda_runtime.h>
#include <cuda_fp16.h>
#include <math.h>
#include <stdint.h>

// ---------------- problem dims ----------------
#define T_TOK 2048
#define H_DIM 1024
#define F_DIM 4096
#define E_NUM 8
#define CAP   2048

// ---------------- GEMM tiling ----------------
#define BM 128
#define BN 128
#define BK 32
#define AS 40     // As row stride in halves (80B): conflict-free ldmatrix
#define BS 136    // Bs row stride in halves (272B): conflict-free ldmatrix.trans

// ---------------- device scratch ----------------
__device__ int    d_cnt[E_NUM];
__device__ int    d_tok[E_NUM * CAP];
__device__ float  d_wt [E_NUM * CAP];
__device__ __half d_x16[T_TOK * H_DIM];                       // x in f16
__device__ __half d_hbuf[(size_t)E_NUM * CAP * F_DIM];        // h in f16 (128 MB)

// ---------------- helpers ----------------
__device__ __forceinline__ uint32_t smem_u32(const void* p) {
    uint32_t a;
    asm("{ .reg .u64 t; cvta.to.shared.u64 t, %1; cvt.u32.u64 %0, t; }" : "=r"(a) : "l"(p));
    return a;
}
__device__ __forceinline__ void ldsm4(uint32_t r[4], uint32_t addr) {
    asm volatile("ldmatrix.sync.aligned.m8n8.x4.shared.b16 {%0,%1,%2,%3}, [%4];"
                 : "=r"(r[0]), "=r"(r[1]), "=r"(r[2]), "=r"(r[3]) : "r"(addr));
}
__device__ __forceinline__ void ldsm4t(uint32_t r[4], uint32_t addr) {
    asm volatile("ldmatrix.sync.aligned.m8n8.x4.trans.shared.b16 {%0,%1,%2,%3}, [%4];"
                 : "=r"(r[0]), "=r"(r[1]), "=r"(r[2]), "=r"(r[3]) : "r"(addr));
}
__device__ __forceinline__ void mma16816(float c[4], const uint32_t a[4],
                                         uint32_t b0, uint32_t b1) {
    asm volatile(
        "mma.sync.aligned.m16n8k16.row.col.f32.f16.f16.f32 "
        "{%0,%1,%2,%3}, {%4,%5,%6,%7}, {%8,%9}, {%0,%1,%2,%3};\n"
        : "+f"(c[0]), "+f"(c[1]), "+f"(c[2]), "+f"(c[3])
        : "r"(a[0]), "r"(a[1]), "r"(a[2]), "r"(a[3]), "r"(b0), "r"(b1));
}

// ---------------- kernel 0: zero out + counters + convert x -> f16 ----------------
__global__ void moe_zero_kernel(const float4* __restrict__ x, float4* __restrict__ out) {
    int i = blockIdx.x * blockDim.x + threadIdx.x;
    if (i < E_NUM) d_cnt[i] = 0;
    int stride = gridDim.x * blockDim.x;
    for (int j = i; j < T_TOK * H_DIM / 4; j += stride) {
        out[j] = make_float4(0.f, 0.f, 0.f, 0.f);
        float4 v = x[j];
        half2 h0 = __floats2half2_rn(v.x, v.y);
        half2 h1 = __floats2half2_rn(v.z, v.w);
        *(half2*)(d_x16 + (size_t)j * 4)     = h0;
        *(half2*)(d_x16 + (size_t)j * 4 + 2) = h1;
    }
}

// ---------------- kernel 1: router (warp per token) ----------------
__global__ __launch_bounds__(256) void moe_router_kernel(
    const float* __restrict__ x, const float* __restrict__ gw, const float* __restrict__ gb)
{
    int t = blockIdx.x * 8 + (threadIdx.x >> 5);
    int lane = threadIdx.x & 31;
    if (t >= T_TOK) return;
    float s[E_NUM];
    #pragma unroll
    for (int e = 0; e < E_NUM; e++) s[e] = 0.f;
    #pragma unroll 4
    for (int j = 0; j < H_DIM / 32; j++) {
        float xv = x[(size_t)t * H_DIM + j * 32 + lane];
        const float4* g = (const float4*)(gw + (size_t)(j * 32 + lane) * E_NUM);
        float4 g0 = g[0], g1 = g[1];
        s[0] += xv * g0.x; s[1] += xv * g0.y; s[2] += xv * g0.z; s[3] += xv * g0.w;
        s[4] += xv * g1.x; s[5] += xv * g1.y; s[6] += xv * g1.z; s[7] += xv * g1.w;
    }
    #pragma unroll
    for (int e = 0; e < E_NUM; e++) {
        #pragma unroll
        for (int o = 16; o; o >>= 1) s[e] += __shfl_xor_sync(0xffffffffu, s[e], o);
    }
    if (lane == 0) {
        float lg[E_NUM];
        #pragma unroll
        for (int e = 0; e < E_NUM; e++) lg[e] = s[e] + gb[e];
        int i1 = 0; float l1 = lg[0];
        #pragma unroll
        for (int e = 1; e < E_NUM; e++) if (lg[e] > l1) { l1 = lg[e]; i1 = e; }
        int i2 = -1; float l2 = -1e30f;
        #pragma unroll
        for (int e = 0; e < E_NUM; e++) if (e != i1 && lg[e] > l2) { l2 = lg[e]; i2 = e; }
        float p1 = 1.0f / (1.0f + expf(l2 - l1));  // renormed top-2 of softmax
        float p2 = 1.0f - p1;
        int q1 = atomicAdd(&d_cnt[i1], 1);
        d_tok[i1 * CAP + q1] = t;  d_wt[i1 * CAP + q1] = p1;
        int q2 = atomicAdd(&d_cnt[i2], 1);
        d_tok[i2 * CAP + q2] = t;  d_wt[i2 * CAP + q2] = p2;
    }
}

// ---------------- kernel 2: GEMM1  h = relu(X_gather @ W1[e] + b1) ----------------
__global__ __launch_bounds__(256, 2) void moe_ffn1_kernel(
    const float* __restrict__ w1, const float* __restrict__ b1)
{
    int e  = blockIdx.z;
    int M  = d_cnt[e];
    int m0 = blockIdx.y * BM;
    if (m0 >= M) return;
    int n0 = blockIdx.x * BN;

    __shared__ __half As[BM * AS];
    __shared__ __half Bs[BK * BS];

    int tid = threadIdx.x, warp = tid >> 5, lane = tid & 31;
    int wm = warp >> 2, wn = warp & 3;          // 2x4 warps, warp tile 64x32
    int grp = lane >> 2, t4 = lane & 3;

    // A load mapping: thread -> (row ar, k-half ah): 2x uint4 (16 halves)
    int ar = tid >> 1, ah = tid & 1;
    int gr = m0 + ar;
    int tokA = d_tok[e * CAP + ((gr < M) ? gr : 0)];
    const uint4* asrc = (const uint4*)(d_x16 + (size_t)tokA * H_DIM) + ah * 2;
    // B load mapping: thread -> (k-row kl, 16 f32 starting at nq)
    int kl = tid >> 3, nq = (tid & 7) * 16;
    const float4* bsrc = (const float4*)(w1 + ((size_t)e * H_DIM + kl) * F_DIM + n0 + nq);
    const size_t bstep = (size_t)BK * F_DIM / 4;

    float acc[4][4][4];
    #pragma unroll
    for (int mi = 0; mi < 4; mi++)
        #pragma unroll
        for (int ni = 0; ni < 4; ni++)
            #pragma unroll
            for (int j = 0; j < 4; j++) acc[mi][ni][j] = 0.f;

    // ldmatrix lane address bases
    uint32_t sA = smem_u32(As), sB = smem_u32(Bs);
    int lrow = lane & 15, lsel = lane >> 4;
    uint32_t aBase = sA + (uint32_t)(((wm * 64 + lrow) * AS + lsel * 8) * 2);
    uint32_t bBase = sB + (uint32_t)((lrow * BS + wn * 32 + lsel * 8) * 2);

    const int NIT = H_DIM / BK;   // 32
    // prologue: prefetch tile 0
    uint4  pa0 = asrc[0], pa1 = asrc[1];
    float4 pb0 = bsrc[0], pb1 = bsrc[1], pb2 = bsrc[2], pb3 = bsrc[3];

    for (int it = 0; it < NIT; ++it) {
        // stores for tile it
        {
            uint4* ad = (uint4*)(As + ar * AS + ah * 16);
            ad[0] = pa0; ad[1] = pa1;
            half2* bd = (half2*)(Bs + kl * BS + nq);
            bd[0] = __floats2half2_rn(pb0.x, pb0.y); bd[1] = __floats2half2_rn(pb0.z, pb0.w);
            bd[2] = __floats2half2_rn(pb1.x, pb1.y); bd[3] = __floats2half2_rn(pb1.z, pb1.w);
            bd[4] = __floats2half2_rn(pb2.x, pb2.y); bd[5] = __floats2half2_rn(pb2.z, pb2.w);
            bd[6] = __floats2half2_rn(pb3.x, pb3.y); bd[7] = __floats2half2_rn(pb3.z, pb3.w);
        }
        __syncthreads();
        if (it + 1 < NIT) {   // prefetch next tile (in flight during mma)
            pa0 = asrc[(it + 1) * 4];     pa1 = asrc[(it + 1) * 4 + 1];
            const float4* bp = bsrc + (size_t)(it + 1) * bstep;
            pb0 = bp[0]; pb1 = bp[1]; pb2 = bp[2]; pb3 = bp[3];
        }
        #pragma unroll
        for (int ks = 0; ks < 2; ks++) {
            uint32_t a[4][4];
            #pragma unroll
            for (int mi = 0; mi < 4; mi++)
                ldsm4(a[mi], aBase + mi * (16 * AS * 2) + ks * 32);
            #pragma unroll
            for (int j = 0; j < 2; j++) {
                uint32_t b[4];
                ldsm4t(b, bBase + ks * (16 * BS * 2) + j * 32);
                #pragma unroll
                for (int mi = 0; mi < 4; mi++) {
                    mma16816(acc[mi][2 * j],     a[mi], b[0], b[1]);
                    mma16816(acc[mi][2 * j + 1], a[mi], b[2], b[3]);
                }
            }
        }
        __syncthreads();
    }

    // epilogue: relu(acc + b1) -> hbuf (f16)
    #pragma unroll
    for (int mi = 0; mi < 4; mi++) {
        int r = m0 + wm * 64 + mi * 16 + grp;
        #pragma unroll
        for (int ni = 0; ni < 4; ni++) {
            int c = n0 + wn * 32 + ni * 8 + t4 * 2;
            float2 bv = *(const float2*)(b1 + (size_t)e * F_DIM + c);
            if (r < M) {
                *(half2*)(d_hbuf + (size_t)(e * CAP + r) * F_DIM + c) =
                    __floats2half2_rn(fmaxf(acc[mi][ni][0] + bv.x, 0.f),
                                      fmaxf(acc[mi][ni][1] + bv.y, 0.f));
            }
            if (r + 8 < M) {
                *(half2*)(d_hbuf + (size_t)(e * CAP + r + 8) * F_DIM + c) =
                    __floats2half2_rn(fmaxf(acc[mi][ni][2] + bv.x, 0.f),
                                      fmaxf(acc[mi][ni][3] + bv.y, 0.f));
            }
        }
    }
}

// ---------------- kernel 3: GEMM2  out[tok] += wt*(h @ W2[e] + b2) ----------------
__global__ __launch_bounds__(256, 2) void moe_ffn2_kernel(
    const float* __restrict__ w2, const float* __restrict__ b2, float* __restrict__ out)
{
    int e  = blockIdx.z;
    int M  = d_cnt[e];
    int m0 = blockIdx.y * BM;
    if (m0 >= M) return;
    int n0 = blockIdx.x * BN;

    __shared__ __half As[BM * AS];
    __shared__ __half Bs[BK * BS];

    int tid = threadIdx.x, warp = tid >> 5, lane = tid & 31;
    int wm = warp >> 2, wn = warp & 3;
    int grp = lane >> 2, t4 = lane & 3;

    int ar = tid >> 1, ah = tid & 1;
    const uint4* asrc = (const uint4*)(d_hbuf + (size_t)(e * CAP + m0 + ar) * F_DIM) + ah * 2;
    int kl = tid >> 3, nq = (tid & 7) * 16;
    const float4* bsrc = (const float4*)(w2 + ((size_t)e * F_DIM + kl) * H_DIM + n0 + nq);
    const size_t bstep = (size_t)BK * H_DIM / 4;

    float acc[4][4][4];
    #pragma unroll
    for (int mi = 0; mi < 4; mi++)
        #pragma unroll
        for (int ni = 0; ni < 4; ni++)
            #pragma unroll
            for (int j = 0; j < 4; j++) acc[mi][ni][j] = 0.f;

    uint32_t sA = smem_u32(As), sB = smem_u32(Bs);
    int lrow = lane & 15, lsel = lane >> 4;
    uint32_t aBase = sA + (uint32_t)(((wm * 64 + lrow) * AS + lsel * 8) * 2);
    uint32_t bBase = sB + (uint32_t)((lrow * BS + wn * 32 + lsel * 8) * 2);

    const int NIT = F_DIM / BK;   // 128
    uint4  pa0 = asrc[0], pa1 = asrc[1];
    float4 pb0 = bsrc[0], pb1 = bsrc[1], pb2 = bsrc[2], pb3 = bsrc[3];

    for (int it = 0; it < NIT; ++it) {
        {
            uint4* ad = (uint4*)(As + ar * AS + ah * 16);
            ad[0] = pa0; ad[1] = pa1;
            half2* bd = (half2*)(Bs + kl * BS + nq);
            bd[0] = __floats2half2_rn(pb0.x, pb0.y); bd[1] = __floats2half2_rn(pb0.z, pb0.w);
            bd[2] = __floats2half2_rn(pb1.x, pb1.y); bd[3] = __floats2half2_rn(pb1.z, pb1.w);
            bd[4] = __floats2half2_rn(pb2.x, pb2.y); bd[5] = __floats2half2_rn(pb2.z, pb2.w);
            bd[6] = __floats2half2_rn(pb3.x, pb3.y); bd[7] = __floats2half2_rn(pb3.z, pb3.w);
        }
        __syncthreads();
        if (it + 1 < NIT) {
            pa0 = asrc[(it + 1) * 4];     pa1 = asrc[(it + 1) * 4 + 1];
            const float4* bp = bsrc + (size_t)(it + 1) * bstep;
            pb0 = bp[0]; pb1 = bp[1]; pb2 = bp[2]; pb3 = bp[3];
        }
        #pragma unroll
        for (int ks = 0; ks < 2; ks++) {
            uint32_t a[4][4];
            #pragma unroll
            for (int mi = 0; mi < 4; mi++)
                ldsm4(a[mi], aBase + mi * (16 * AS * 2) + ks * 32);
            #pragma unroll
            for (int j = 0; j < 2; j++) {
                uint32_t b[4];
                ldsm4t(b, bBase + ks * (16 * BS * 2) + j * 32);
                #pragma unroll
                for (int mi = 0; mi < 4; mi++) {
                    mma16816(acc[mi][2 * j],     a[mi], b[0], b[1]);
                    mma16816(acc[mi][2 * j + 1], a[mi], b[2], b[3]);
                }
            }
        }
        __syncthreads();
    }

    // epilogue: scatter wt*(acc + b2) into out (2 atomic adds per out element total)
    #pragma unroll
    for (int mi = 0; mi < 4; mi++) {
        int r = m0 + wm * 64 + mi * 16 + grp;
        bool v0 = (r < M), v1 = (r + 8 < M);
        int tok0 = 0, tok1 = 0; float wt0 = 0.f, wt1 = 0.f;
        if (v0) { tok0 = d_tok[e * CAP + r];     wt0 = d_wt[e * CAP + r]; }
        if (v1) { tok1 = d_tok[e * CAP + r + 8]; wt1 = d_wt[e * CAP + r + 8]; }
        #pragma unroll
        for (int ni = 0; ni < 4; ni++) {
            int c = n0 + wn * 32 + ni * 8 + t4 * 2;
            float2 bv = *(const float2*)(b2 + (size_t)e * H_DIM + c);
            if (v0) {
                atomicAdd(out + (size_t)tok0 * H_DIM + c,     wt0 * (acc[mi][ni][0] + bv.x));
                atomicAdd(out + (size_t)tok0 * H_DIM + c + 1, wt0 * (acc[mi][ni][1] + bv.y));
            }
            if (v1) {
                atomicAdd(out + (size_t)tok1 * H_DIM + c,     wt1 * (acc[mi][ni][2] + bv.x));
                atomicAdd(out + (size_t)tok1 * H_DIM + c + 1, wt1 * (acc[mi][ni][3] + bv.y));
            }
        }
    }
}

// ---------------- launch ----------------
extern "C" void kernel_launch(void* const* d_in, const int* in_sizes, int n_in,
                              void* d_out, int out_size) {
    const float* x  = (const float*)d_in[0];
    const float* gw = (const float*)d_in[1];
    const float* gb = (const float*)d_in[2];
    const float* w1 = (const float*)d_in[3];
    const float* b1 = (const float*)d_in[4];
    const float* w2 = (const float*)d_in[5];
    const float* b2 = (const float*)d_in[6];
    float* out = (float*)d_out;

    moe_zero_kernel<<<512, 256>>>((const float4*)x, (float4*)d_out);
    moe_router_kernel<<<T_TOK / 8, 256>>>(x, gw, gb);
    dim3 g1(F_DIM / BN, CAP / BM, E_NUM);
    moe_ffn1_kernel<<<g1, 256>>>(w1, b1);
    dim3 g2(H_DIM / BN, CAP / BM, E_NUM);
    moe_ffn2_kernel<<<g2, 256>>>(w2, b2, out);
}